// round 7
// baseline (speedup 1.0000x reference)
#include <cuda_runtime.h>
#include <cuda_bf16.h>
#include <cstdint>
#include <math.h>

// ---------------------------------------------------------------------------
// Problem constants
// ---------------------------------------------------------------------------
#define BQ 8
#define NQ 2048
#define DQ 512
#define MTOT (BQ * NQ)   // 16384

// ---------------------------------------------------------------------------
// Device scratch (no runtime allocation allowed)
// ---------------------------------------------------------------------------
__device__ __nv_bfloat16 g_x_hi[MTOT * DQ], g_x_lo[MTOT * DQ];
__device__ __nv_bfloat16 g_w_hi[DQ * DQ],   g_w_lo[DQ * DQ];
__device__ __nv_bfloat16 g_at_hi[DQ * DQ],  g_at_lo[DQ * DQ];     // attn^T
__device__ __nv_bfloat16 g_h_hi[MTOT * DQ],  g_h_lo[MTOT * DQ];
__device__ __nv_bfloat16 g_ht_hi[MTOT * DQ], g_ht_lo[MTOT * DQ];  // per-batch H^T
__device__ __nv_bfloat16 g_ha_hi[MTOT * DQ], g_ha_lo[MTOT * DQ];
__device__ __nv_bfloat16 g_p_hi[(size_t)BQ * NQ * NQ], g_p_lo[(size_t)BQ * NQ * NQ];
__device__ float g_s[(size_t)BQ * NQ * NQ];

// ---------------------------------------------------------------------------
// Low-level helpers (base compute_103 features only)
// ---------------------------------------------------------------------------
__device__ __forceinline__ uint32_t smem_u32(const void* p) {
    uint32_t a;
    asm("{ .reg .u64 t; cvta.to.shared.u64 t, %1; cvt.u32.u64 %0, t; }" : "=r"(a) : "l"(p));
    return a;
}

#define CP16(dst, src) \
    asm volatile("cp.async.cg.shared.global [%0], [%1], 16;\n" :: "r"(dst), "l"(src) : "memory")
#define CP_COMMIT() asm volatile("cp.async.commit_group;\n" ::: "memory")
#define CP_WAIT1()  asm volatile("cp.async.wait_group 1;\n" ::: "memory")

__device__ __forceinline__ void ldsm4(uint32_t* r, uint32_t addr) {
    asm volatile("ldmatrix.sync.aligned.m8n8.x4.shared.b16 {%0,%1,%2,%3}, [%4];\n"
                 : "=r"(r[0]), "=r"(r[1]), "=r"(r[2]), "=r"(r[3]) : "r"(addr));
}

__device__ __forceinline__ void mma16816(float* c, const uint32_t* a, const uint32_t* b) {
    asm volatile(
        "mma.sync.aligned.m16n8k16.row.col.f32.bf16.bf16.f32 "
        "{%0,%1,%2,%3}, {%4,%5,%6,%7}, {%8,%9}, {%0,%1,%2,%3};\n"
        : "+f"(c[0]), "+f"(c[1]), "+f"(c[2]), "+f"(c[3])
        : "r"(a[0]), "r"(a[1]), "r"(a[2]), "r"(a[3]), "r"(b[0]), "r"(b[1]));
}

// ---------------------------------------------------------------------------
// SMEM: per stage A tile 128 rows x 128B, B tile 128 rows x 128B.
// A row packs [hi k0..k31 (64B) | lo k0..k31 (64B)] for a BK=32 slice.
// XOR swizzle: phys = row*128 + (off ^ ((row&7)<<4)).
// ---------------------------------------------------------------------------
#define A_SB      16384
#define B_SB      16384
#define STAGE_SB  (A_SB + B_SB)         // 32768
#define NSTAGE    3
#define SMEM_GEMM (NSTAGE * STAGE_SB)   // 98304

__device__ __forceinline__ uint32_t swz(uint32_t row, uint32_t off) {
    return row * 128 + (off ^ ((row & 7) << 4));
}

// issue one stage: 128 threads, per thread 16 cp.async of 16B (A:8, B:8)
__device__ __forceinline__ void issue_stage(
    uint32_t sd, const char* Ah, const char* Al, const char* Bh, const char* Bl,
    int lda_b, int ldb_b, int kb /*bytes = s*64*/, int tid)
{
    const uint32_t row0 = tid >> 3;           // 0..15
    const uint32_t c = tid & 7;               // 16B chunk within 128B row
    const uint32_t off = c * 16;
    const char* srcA = (c < 4) ? Ah : Al;
    const char* srcB = (c < 4) ? Bh : Bl;
    const int cb = (c & 3) * 16;
#pragma unroll
    for (int blk = 0; blk < 8; ++blk) {
        const uint32_t row = row0 + blk * 16;
        CP16(sd + swz(row, off),        srcA + (size_t)row * lda_b + kb + cb);
        CP16(sd + A_SB + swz(row, off), srcB + (size_t)row * ldb_b + kb + cb);
    }
}

// ---------------------------------------------------------------------------
// Unified HMMA GEMM: C[m,n] = sum_k A[m,k] * B[n,k] via bf16 split 3-pass
// CTA tile 128x128, 128 threads = 4 warps (2 along M x 2 along N), warp 64x64.
// Pipelined mainloop: B-fragment double buffering; LDGSTS issued inside the
// ks0 ldsm latency window so the tensor pipe never idles on LSU work.
// MODE 1: out = C + bias -> h hi/lo      (M=16384, N=512, K=512)
// MODE 2: out = C        -> ha hi/lo     (M=16384, N=512, K=512)
// MODE 3: out = mask(C)  -> scores fp32  (per batch, M=N=2048, K=512)
// MODE 4: out = elu(C)   -> out fp32     (per batch, M=2048, N=512, K=2048)
// ---------------------------------------------------------------------------
template <int MODE>
__global__ __launch_bounds__(128, 2) void k_mma(
    const __nv_bfloat16* __restrict__ Ahi, const __nv_bfloat16* __restrict__ Alo,
    const __nv_bfloat16* __restrict__ Bhi, const __nv_bfloat16* __restrict__ Blo,
    const float* __restrict__ bias, const int* __restrict__ adj,
    float* __restrict__ outf,
    __nv_bfloat16* __restrict__ out_hi, __nv_bfloat16* __restrict__ out_lo)
{
    constexpr int KDIM = (MODE == 4) ? 2048 : 512;
    constexpr int LDA  = (MODE == 4) ? 2048 : 512;
    constexpr int LDB  = (MODE == 4) ? 2048 : 512;
    constexpr int NST  = KDIM / 32;

    extern __shared__ char smem[];
    const uint32_t sbase = smem_u32(smem);
    const int tid = threadIdx.x;
    const int lane = tid & 31, wid = tid >> 5;
    const int warp_m = wid & 1;        // 2 warps along M (64 rows each)
    const int warp_n = wid >> 1;       // 2 warps along N (64 cols each)

    const int bn = blockIdx.x * 128, bm = blockIdx.y * 128, z = blockIdx.z;
    size_t aoff = 0, boff = 0;
    if (MODE == 3) { aoff = (size_t)z * NQ * DQ; boff = (size_t)z * NQ * DQ; }
    if (MODE == 4) { aoff = (size_t)z * NQ * NQ; boff = (size_t)z * DQ * NQ; }

    const char* A0h = (const char*)(Ahi + aoff + (size_t)bm * LDA);
    const char* A0l = (const char*)(Alo + aoff + (size_t)bm * LDA);
    const char* B0h = (const char*)(Bhi + boff + (size_t)bn * LDB);
    const char* B0l = (const char*)(Blo + boff + (size_t)bn * LDB);

    // per-lane ldmatrix row bases (A: 4 m16 tiles, B: 4 n16 groups)
    uint32_t a_rt[4], a_sw[4];
#pragma unroll
    for (int mi = 0; mi < 4; ++mi) {
        const uint32_t r = warp_m * 64 + mi * 16 + (lane & 15);
        a_rt[mi] = r * 128; a_sw[mi] = (r & 7) << 4;
    }
    uint32_t b_rt[4], b_sw[4];
    {
        const uint32_t brow = (lane & 7) + ((lane >> 4) & 1) * 8;
#pragma unroll
        for (int jp = 0; jp < 4; ++jp) {
            const uint32_t r = warp_n * 64 + jp * 16 + brow;
            b_rt[jp] = r * 128; b_sw[jp] = (r & 7) << 4;
        }
    }
    const uint32_t a_koff = (lane >> 4) * 16;        // 0 or 16
    const uint32_t b_koff = ((lane >> 3) & 1) * 16;  // 0 or 16

    float acc[4][8][4];
#pragma unroll
    for (int i = 0; i < 4; ++i)
#pragma unroll
        for (int j = 0; j < 8; ++j)
#pragma unroll
            for (int k = 0; k < 4; ++k) acc[i][j][k] = 0.f;

    // prologue: stages 0, 1
    issue_stage(sbase,            A0h, A0l, B0h, B0l, LDA*2, LDB*2, 0,  tid);
    CP_COMMIT();
    issue_stage(sbase + STAGE_SB, A0h, A0l, B0h, B0l, LDA*2, LDB*2, 64, tid);
    CP_COMMIT();

    int buf = 0, nbuf = 2;   // buf = stage i % 3; nbuf = (i+2) % 3
    for (int i = 0; i < NST; ++i) {
        CP_WAIT1();
        __syncthreads();

        const uint32_t sa = sbase + buf * STAGE_SB;
        const uint32_t sb = sa + A_SB;

        uint32_t ah[4][4], al[4][4];
        uint32_t bh[2][4], bl[2][4];

#pragma unroll
        for (int ks = 0; ks < 2; ++ks) {
            const uint32_t ko = ks * 32;
            // A fragments for this k16
#pragma unroll
            for (int mi = 0; mi < 4; ++mi) {
                ldsm4(ah[mi], sa + a_rt[mi] + ((ko + a_koff)      ^ a_sw[mi]));
                ldsm4(al[mi], sa + a_rt[mi] + ((ko + a_koff + 64) ^ a_sw[mi]));
            }
            if (ks == 0) {
                // issue next-next stage inside the ldsm latency window
                if (i + 2 < NST)
                    issue_stage(sbase + nbuf * STAGE_SB, A0h, A0l, B0h, B0l,
                                LDA*2, LDB*2, (i + 2) * 64, tid);
                CP_COMMIT();   // empty group when not issuing keeps wait_group 1 exact
            }
            // B fragment double buffering: load jp+1 before MMAs of jp
            ldsm4(bh[0], sb + b_rt[0] + ((ko + b_koff)      ^ b_sw[0]));
            ldsm4(bl[0], sb + b_rt[0] + ((ko + b_koff + 64) ^ b_sw[0]));
#pragma unroll
            for (int jp = 0; jp < 4; ++jp) {
                const int cu = jp & 1, nx = cu ^ 1;
                if (jp < 3) {
                    ldsm4(bh[nx], sb + b_rt[jp+1] + ((ko + b_koff)      ^ b_sw[jp+1]));
                    ldsm4(bl[nx], sb + b_rt[jp+1] + ((ko + b_koff + 64) ^ b_sw[jp+1]));
                }
#pragma unroll
                for (int mi = 0; mi < 4; ++mi) {
                    mma16816(acc[mi][2*jp],   ah[mi], bh[cu]);
                    mma16816(acc[mi][2*jp],   ah[mi], bl[cu]);
                    mma16816(acc[mi][2*jp],   al[mi], bh[cu]);
                    mma16816(acc[mi][2*jp+1], ah[mi], bh[cu] + 2);
                    mma16816(acc[mi][2*jp+1], ah[mi], bl[cu] + 2);
                    mma16816(acc[mi][2*jp+1], al[mi], bh[cu] + 2);
                }
            }
        }
        buf = (buf == 2) ? 0 : buf + 1;
        nbuf = (nbuf == 2) ? 0 : nbuf + 1;
    }

    // -----------------------------------------------------------------------
    // Epilogue: direct fragment stores (pairs contiguous in n)
    // -----------------------------------------------------------------------
    const int rbase = bm + warp_m * 64 + (lane >> 2);
    const int cbase = bn + warp_n * 64 + (lane & 3) * 2;

#pragma unroll
    for (int mi = 0; mi < 4; ++mi) {
#pragma unroll
        for (int j = 0; j < 8; ++j) {
            const int gc = cbase + j * 8;
#pragma unroll
            for (int half = 0; half < 2; ++half) {
                const int gr = rbase + mi * 16 + half * 8;
                float v0 = acc[mi][j][half * 2 + 0];
                float v1 = acc[mi][j][half * 2 + 1];
                if (MODE == 1) {
                    const float2 bv = *(const float2*)(bias + gc);
                    v0 += bv.x; v1 += bv.y;
                }
                if (MODE == 1 || MODE == 2) {
                    const __nv_bfloat16 h0 = __float2bfloat16(v0);
                    const __nv_bfloat16 h1 = __float2bfloat16(v1);
                    __nv_bfloat162 hp; hp.x = h0; hp.y = h1;
                    __nv_bfloat162 lp;
                    lp.x = __float2bfloat16(v0 - __bfloat162float(h0));
                    lp.y = __float2bfloat16(v1 - __bfloat162float(h1));
                    *(__nv_bfloat162*)(out_hi + (size_t)gr * DQ + gc) = hp;
                    *(__nv_bfloat162*)(out_lo + (size_t)gr * DQ + gc) = lp;
                } else if (MODE == 3) {
                    const size_t o = (size_t)z * NQ * NQ + (size_t)gr * NQ + gc;
                    const int2 ad = *(const int2*)(adj + o);
                    float2 ov;
                    ov.x = ad.x ? v0 : -1e30f;
                    ov.y = ad.y ? v1 : -1e30f;
                    *(float2*)(outf + o) = ov;
                } else {
                    const size_t o = (size_t)z * NQ * DQ + (size_t)gr * DQ + gc;
                    float2 ov;
                    ov.x = (v0 > 0.f) ? v0 : expm1f(v0);
                    ov.y = (v1 > 0.f) ? v1 : expm1f(v1);
                    *(float2*)(outf + o) = ov;
                }
            }
        }
    }
}

// ---------------------------------------------------------------------------
// fp32 -> bf16 hi/lo split (elementwise)
// ---------------------------------------------------------------------------
__global__ __launch_bounds__(256) void k_split(
    const float* __restrict__ in, __nv_bfloat16* __restrict__ hi,
    __nv_bfloat16* __restrict__ lo, int n)
{
    for (int i = blockIdx.x * 256 + threadIdx.x; i < n; i += gridDim.x * 256) {
        const float v = in[i];
        const __nv_bfloat16 h = __float2bfloat16(v);
        hi[i] = h;
        lo[i] = __float2bfloat16(v - __bfloat162float(h));
    }
}

// attn [K,N] fp32 -> attn^T [N,K] bf16 hi/lo
__global__ __launch_bounds__(256) void k_split_T(
    const float* __restrict__ in, __nv_bfloat16* __restrict__ hi,
    __nv_bfloat16* __restrict__ lo)
{
    for (int i = blockIdx.x * 256 + threadIdx.x; i < DQ * DQ; i += gridDim.x * 256) {
        const int n = i / DQ, k = i % DQ;
        const float v = in[(size_t)k * DQ + n];
        const __nv_bfloat16 h = __float2bfloat16(v);
        hi[i] = h;
        lo[i] = __float2bfloat16(v - __bfloat162float(h));
    }
}

// h [b,n,d] bf16 -> hT [b,d,n] bf16 (hi and lo)
__global__ __launch_bounds__(256) void k_transpose(
    const __nv_bfloat16* __restrict__ hi, const __nv_bfloat16* __restrict__ lo,
    __nv_bfloat16* __restrict__ thi, __nv_bfloat16* __restrict__ tlo)
{
    __shared__ __nv_bfloat16 t0[32][33], t1[32][33];
    const int b = blockIdx.z;
    const int n0 = blockIdx.x * 32, d0 = blockIdx.y * 32;
    const int tx = threadIdx.x & 31, ty = threadIdx.x >> 5;   // 32 x 8
#pragma unroll
    for (int j = 0; j < 32; j += 8) {
        const size_t idx = ((size_t)b * NQ + n0 + ty + j) * DQ + d0 + tx;
        t0[ty + j][tx] = hi[idx];
        t1[ty + j][tx] = lo[idx];
    }
    __syncthreads();
#pragma unroll
    for (int j = 0; j < 32; j += 8) {
        const size_t o = ((size_t)b * DQ + d0 + ty + j) * NQ + n0 + tx;
        thi[o] = t0[tx][ty + j];
        tlo[o] = t1[tx][ty + j];
    }
}

// ---------------------------------------------------------------------------
// Row softmax over scores -> P bf16 hi/lo
// ---------------------------------------------------------------------------
__global__ __launch_bounds__(256) void k_softmax(
    const float* __restrict__ S, __nv_bfloat16* __restrict__ Phi,
    __nv_bfloat16* __restrict__ Plo)
{
    __shared__ float red[256];
    const size_t base = (size_t)blockIdx.x * NQ;
    const int tid = threadIdx.x;

    float v[8];
    float m = -INFINITY;
#pragma unroll
    for (int i = 0; i < 8; ++i) {
        v[i] = S[base + tid + i * 256];
        m = fmaxf(m, v[i]);
    }
    red[tid] = m;
    __syncthreads();
    for (int s = 128; s > 0; s >>= 1) {
        if (tid < s) red[tid] = fmaxf(red[tid], red[tid + s]);
        __syncthreads();
    }
    m = red[0];
    __syncthreads();

    float sum = 0.f;
#pragma unroll
    for (int i = 0; i < 8; ++i) {
        v[i] = expf(v[i] - m);
        sum += v[i];
    }
    red[tid] = sum;
    __syncthreads();
    for (int s = 128; s > 0; s >>= 1) {
        if (tid < s) red[tid] += red[tid + s];
        __syncthreads();
    }
    const float inv = 1.f / red[0];
#pragma unroll
    for (int i = 0; i < 8; ++i) {
        const float w = v[i] * inv;
        const __nv_bfloat16 h = __float2bfloat16(w);
        Phi[base + tid + i * 256] = h;
        Plo[base + tid + i * 256] = __float2bfloat16(w - __bfloat162float(h));
    }
}

// ---------------------------------------------------------------------------
// Launch
// ---------------------------------------------------------------------------
extern "C" void kernel_launch(void* const* d_in, const int* in_sizes, int n_in,
                              void* d_out, int out_size)
{
    const float* x    = (const float*)d_in[0];
    const int*   adj  = (const int*)  d_in[1];
    const float* W    = (const float*)d_in[2];
    const float* bias = (const float*)d_in[3];
    const float* attn = (const float*)d_in[4];
    float* out = (float*)d_out;

    __nv_bfloat16 *x_hi, *x_lo, *w_hi, *w_lo, *at_hi, *at_lo;
    __nv_bfloat16 *h_hi, *h_lo, *ht_hi, *ht_lo, *ha_hi, *ha_lo, *p_hi, *p_lo;
    float* s;
    cudaGetSymbolAddress((void**)&x_hi,  g_x_hi);  cudaGetSymbolAddress((void**)&x_lo,  g_x_lo);
    cudaGetSymbolAddress((void**)&w_hi,  g_w_hi);  cudaGetSymbolAddress((void**)&w_lo,  g_w_lo);
    cudaGetSymbolAddress((void**)&at_hi, g_at_hi); cudaGetSymbolAddress((void**)&at_lo, g_at_lo);
    cudaGetSymbolAddress((void**)&h_hi,  g_h_hi);  cudaGetSymbolAddress((void**)&h_lo,  g_h_lo);
    cudaGetSymbolAddress((void**)&ht_hi, g_ht_hi); cudaGetSymbolAddress((void**)&ht_lo, g_ht_lo);
    cudaGetSymbolAddress((void**)&ha_hi, g_ha_hi); cudaGetSymbolAddress((void**)&ha_lo, g_ha_lo);
    cudaGetSymbolAddress((void**)&p_hi,  g_p_hi);  cudaGetSymbolAddress((void**)&p_lo,  g_p_lo);
    cudaGetSymbolAddress((void**)&s,     g_s);

    cudaFuncSetAttribute(k_mma<1>, cudaFuncAttributeMaxDynamicSharedMemorySize, SMEM_GEMM);
    cudaFuncSetAttribute(k_mma<2>, cudaFuncAttributeMaxDynamicSharedMemorySize, SMEM_GEMM);
    cudaFuncSetAttribute(k_mma<3>, cudaFuncAttributeMaxDynamicSharedMemorySize, SMEM_GEMM);
    cudaFuncSetAttribute(k_mma<4>, cudaFuncAttributeMaxDynamicSharedMemorySize, SMEM_GEMM);

    // Input splits
    k_split<<<4096, 256>>>(x, x_hi, x_lo, MTOT * DQ);
    k_split<<<512, 256>>>(W, w_hi, w_lo, DQ * DQ);
    k_split_T<<<512, 256>>>(attn, at_hi, at_lo);

    // h = x @ W^T + b
    k_mma<1><<<dim3(DQ / 128, MTOT / 128, 1), 128, SMEM_GEMM>>>(
        x_hi, x_lo, w_hi, w_lo, bias, nullptr, nullptr, h_hi, h_lo);

    // hT per batch
    k_transpose<<<dim3(NQ / 32, DQ / 32, BQ), 256>>>(h_hi, h_lo, ht_hi, ht_lo);

    // ha = h @ attn
    k_mma<2><<<dim3(DQ / 128, MTOT / 128, 1), 128, SMEM_GEMM>>>(
        h_hi, h_lo, at_hi, at_lo, nullptr, nullptr, nullptr, ha_hi, ha_lo);

    // scores = ha @ h^T (per batch), adjacency-masked
    k_mma<3><<<dim3(NQ / 128, NQ / 128, BQ), 128, SMEM_GEMM>>>(
        ha_hi, ha_lo, h_hi, h_lo, nullptr, adj, s, nullptr, nullptr);

    // softmax rows -> P hi/lo
    k_softmax<<<BQ * NQ, 256>>>(s, p_hi, p_lo);

    // out = elu(P @ h) per batch
    k_mma<4><<<dim3(DQ / 128, NQ / 128, BQ), 128, SMEM_GEMM>>>(
        p_hi, p_lo, ht_hi, ht_lo, nullptr, nullptr, out, nullptr, nullptr);
}

// round 8
// speedup vs baseline: 1.1707x; 1.1707x over previous
#include <cuda_runtime.h>
#include <cuda_fp16.h>
#include <cstdint>
#include <math.h>

// ---------------------------------------------------------------------------
// Problem constants
// ---------------------------------------------------------------------------
#define BQ 8
#define NQ 2048
#define DQ 512
#define MTOT (BQ * NQ)   // 16384

// ---------------------------------------------------------------------------
// Device scratch (no runtime allocation allowed)
// ---------------------------------------------------------------------------
__device__ __half g_x_hi[MTOT * DQ], g_x_lo[MTOT * DQ];
__device__ __half g_w_hi[DQ * DQ],   g_w_lo[DQ * DQ];
__device__ __half g_at_hi[DQ * DQ],  g_at_lo[DQ * DQ];     // attn^T
__device__ __half g_h_hi[MTOT * DQ],  g_h_lo[MTOT * DQ];
__device__ __half g_ht_hi[MTOT * DQ], g_ht_lo[MTOT * DQ];  // per-batch H^T
__device__ __half g_ha_hi[MTOT * DQ], g_ha_lo[MTOT * DQ];
__device__ __half g_p[(size_t)BQ * NQ * NQ];               // softmax weights, fp16
__device__ float g_s[(size_t)BQ * NQ * NQ];

// ---------------------------------------------------------------------------
// Low-level helpers (base compute_103 features only)
// ---------------------------------------------------------------------------
__device__ __forceinline__ uint32_t smem_u32(const void* p) {
    uint32_t a;
    asm("{ .reg .u64 t; cvta.to.shared.u64 t, %1; cvt.u32.u64 %0, t; }" : "=r"(a) : "l"(p));
    return a;
}

#define CP16(dst, src) \
    asm volatile("cp.async.cg.shared.global [%0], [%1], 16;\n" :: "r"(dst), "l"(src) : "memory")
#define CP_COMMIT() asm volatile("cp.async.commit_group;\n" ::: "memory")
#define CP_WAIT1()  asm volatile("cp.async.wait_group 1;\n" ::: "memory")

__device__ __forceinline__ void ldsm4(uint32_t* r, uint32_t addr) {
    asm volatile("ldmatrix.sync.aligned.m8n8.x4.shared.b16 {%0,%1,%2,%3}, [%4];\n"
                 : "=r"(r[0]), "=r"(r[1]), "=r"(r[2]), "=r"(r[3]) : "r"(addr));
}

__device__ __forceinline__ void mma16816(float* c, const uint32_t* a, const uint32_t* b) {
    asm volatile(
        "mma.sync.aligned.m16n8k16.row.col.f32.f16.f16.f32 "
        "{%0,%1,%2,%3}, {%4,%5,%6,%7}, {%8,%9}, {%0,%1,%2,%3};\n"
        : "+f"(c[0]), "+f"(c[1]), "+f"(c[2]), "+f"(c[3])
        : "r"(a[0]), "r"(a[1]), "r"(a[2]), "r"(a[3]), "r"(b[0]), "r"(b[1]));
}

// ---------------------------------------------------------------------------
// Unified HMMA GEMM: C[m,n] = sum_k A[m,k] * B[n,k] via fp16 split
// CTA tile 128x128, 128 threads = 4 warps (2 along M x 2 along N), warp 64x64.
// MODE 1: 3-pass, out = C + bias -> h hi/lo      (M=16384, N=512, K=512)
// MODE 2: 3-pass, out = C        -> ha hi/lo     (M=16384, N=512, K=512)
// MODE 3: 3-pass, out = mask(C)  -> scores fp32  (per batch, M=N=2048, K=512)
// MODE 4: 2-pass (A = P single fp16, B = h^T hi/lo), out = elu(C) -> fp32
//         (per batch, M=2048, N=512, K=2048)
// SMEM swizzles: 128B rows phys = row*128 + (off ^ ((row&7)<<4));
//                64B rows (MODE4 A) phys = row*64 + (off ^ ((row&3)<<4)).
// ---------------------------------------------------------------------------
template <int MODE>
__global__ __launch_bounds__(128, 2) void k_mma(
    const __half* __restrict__ Ahi, const __half* __restrict__ Alo,
    const __half* __restrict__ Bhi, const __half* __restrict__ Blo,
    const float* __restrict__ bias, const int* __restrict__ adj,
    float* __restrict__ outf,
    __half* __restrict__ out_hi, __half* __restrict__ out_lo)
{
    constexpr bool ALO = (MODE != 4);          // does A have a lo part?
    constexpr int KDIM = (MODE == 4) ? 2048 : 512;
    constexpr int LDA  = (MODE == 4) ? 2048 : 512;
    constexpr int LDB  = (MODE == 4) ? 2048 : 512;
    constexpr int NST  = KDIM / 32;
    constexpr int ASB  = ALO ? 16384 : 8192;   // A tile bytes
    constexpr int STG  = ASB + 16384;          // stage bytes (B tile = 16K)

    extern __shared__ char smem[];
    const uint32_t sbase = smem_u32(smem);
    const int tid = threadIdx.x;
    const int lane = tid & 31, wid = tid >> 5;
    const int warp_m = wid & 1;        // 2 warps along M (64 rows each)
    const int warp_n = wid >> 1;       // 2 warps along N (64 cols each)

    const int bn = blockIdx.x * 128, bm = blockIdx.y * 128, z = blockIdx.z;
    size_t aoff = 0, boff = 0;
    if (MODE == 3) { aoff = (size_t)z * NQ * DQ; boff = (size_t)z * NQ * DQ; }
    if (MODE == 4) { aoff = (size_t)z * NQ * NQ; boff = (size_t)z * DQ * NQ; }

    const char* A0h = (const char*)(Ahi + aoff + (size_t)bm * LDA);
    const char* A0l = (const char*)(Alo + aoff + (size_t)bm * LDA);
    const char* B0h = (const char*)(Bhi + boff + (size_t)bn * LDB);
    const char* B0l = (const char*)(Blo + boff + (size_t)bn * LDB);

    // stage loader (lambda over constexpr layout)
    auto issue_stage = [&](uint32_t sd, int kb) {
        // B tile: 128 rows x 128B [hi|lo]
        {
            const uint32_t row0 = tid >> 3;
            const uint32_t c = tid & 7;
            const uint32_t off = c * 16;
            const char* srcB = (c < 4) ? B0h : B0l;
            const int cb = (c & 3) * 16;
#pragma unroll
            for (int blk = 0; blk < 8; ++blk) {
                const uint32_t row = row0 + blk * 16;
                CP16(sd + ASB + row * 128 + (off ^ ((row & 7) << 4)),
                     srcB + (size_t)row * (LDB * 2) + kb + cb);
            }
        }
        if (ALO) {
            // A tile: 128 rows x 128B [hi|lo]
            const uint32_t row0 = tid >> 3;
            const uint32_t c = tid & 7;
            const uint32_t off = c * 16;
            const char* srcA = (c < 4) ? A0h : A0l;
            const int cb = (c & 3) * 16;
#pragma unroll
            for (int blk = 0; blk < 8; ++blk) {
                const uint32_t row = row0 + blk * 16;
                CP16(sd + row * 128 + (off ^ ((row & 7) << 4)),
                     srcA + (size_t)row * (LDA * 2) + kb + cb);
            }
        } else {
            // A tile: 128 rows x 64B [hi only]
            const uint32_t row0 = tid >> 2;
            const uint32_t c = tid & 3;
            const uint32_t off = c * 16;
#pragma unroll
            for (int blk = 0; blk < 4; ++blk) {
                const uint32_t row = row0 + blk * 32;
                CP16(sd + row * 64 + (off ^ ((row & 3) << 4)),
                     A0h + (size_t)row * (LDA * 2) + kb + c * 16);
            }
        }
    };

    // per-lane ldmatrix row bases (A: 4 m16 tiles, B: 4 n16 groups)
    uint32_t a_rt[4], a_sw[4];
#pragma unroll
    for (int mi = 0; mi < 4; ++mi) {
        const uint32_t r = warp_m * 64 + mi * 16 + (lane & 15);
        if (ALO) { a_rt[mi] = r * 128; a_sw[mi] = (r & 7) << 4; }
        else     { a_rt[mi] = r * 64;  a_sw[mi] = (r & 3) << 4; }
    }
    uint32_t b_rt[4], b_sw[4];
    {
        const uint32_t brow = (lane & 7) + ((lane >> 4) & 1) * 8;
#pragma unroll
        for (int jp = 0; jp < 4; ++jp) {
            const uint32_t r = warp_n * 64 + jp * 16 + brow;
            b_rt[jp] = r * 128; b_sw[jp] = (r & 7) << 4;
        }
    }
    const uint32_t a_koff = (lane >> 4) * 16;        // 0 or 16
    const uint32_t b_koff = ((lane >> 3) & 1) * 16;  // 0 or 16

    float acc[4][8][4];
#pragma unroll
    for (int i = 0; i < 4; ++i)
#pragma unroll
        for (int j = 0; j < 8; ++j)
#pragma unroll
            for (int k = 0; k < 4; ++k) acc[i][j][k] = 0.f;

    // prologue: stages 0, 1
    issue_stage(sbase, 0);
    CP_COMMIT();
    issue_stage(sbase + STG, 64);
    CP_COMMIT();

    int buf = 0, nbuf = 2;   // buf = stage i % 3; nbuf = (i+2) % 3
    for (int i = 0; i < NST; ++i) {
        CP_WAIT1();
        __syncthreads();
        if (i + 2 < NST)
            issue_stage(sbase + nbuf * STG, (i + 2) * 64);
        CP_COMMIT();   // empty group when not issuing keeps wait_group 1 exact

        const uint32_t sa = sbase + buf * STG;
        const uint32_t sb = sa + ASB;
#pragma unroll
        for (int ks = 0; ks < 2; ++ks) {
            const uint32_t ko = ks * 32;
            uint32_t ah[4][4], al[4][4];
#pragma unroll
            for (int mi = 0; mi < 4; ++mi) {
                ldsm4(ah[mi], sa + a_rt[mi] + ((ko + a_koff)      ^ a_sw[mi]));
                if (ALO)
                    ldsm4(al[mi], sa + a_rt[mi] + ((ko + a_koff + 64) ^ a_sw[mi]));
            }
#pragma unroll
            for (int jp = 0; jp < 4; ++jp) {
                uint32_t bh[4], bl[4];
                ldsm4(bh, sb + b_rt[jp] + ((ko + b_koff)      ^ b_sw[jp]));
                ldsm4(bl, sb + b_rt[jp] + ((ko + b_koff + 64) ^ b_sw[jp]));
#pragma unroll
                for (int mi = 0; mi < 4; ++mi) {
                    mma16816(acc[mi][2*jp],   ah[mi], bh);
                    mma16816(acc[mi][2*jp],   ah[mi], bl);
                    if (ALO) mma16816(acc[mi][2*jp], al[mi], bh);
                    mma16816(acc[mi][2*jp+1], ah[mi], bh + 2);
                    mma16816(acc[mi][2*jp+1], ah[mi], bl + 2);
                    if (ALO) mma16816(acc[mi][2*jp+1], al[mi], bh + 2);
                }
            }
        }
        buf = (buf == 2) ? 0 : buf + 1;
        nbuf = (nbuf == 2) ? 0 : nbuf + 1;
    }

    // -----------------------------------------------------------------------
    // Epilogue: direct fragment stores (pairs contiguous in n)
    // -----------------------------------------------------------------------
    const int rbase = bm + warp_m * 64 + (lane >> 2);
    const int cbase = bn + warp_n * 64 + (lane & 3) * 2;

#pragma unroll
    for (int mi = 0; mi < 4; ++mi) {
#pragma unroll
        for (int j = 0; j < 8; ++j) {
            const int gc = cbase + j * 8;
#pragma unroll
            for (int half = 0; half < 2; ++half) {
                const int gr = rbase + mi * 16 + half * 8;
                float v0 = acc[mi][j][half * 2 + 0];
                float v1 = acc[mi][j][half * 2 + 1];
                if (MODE == 1) {
                    const float2 bv = *(const float2*)(bias + gc);
                    v0 += bv.x; v1 += bv.y;
                }
                if (MODE == 1 || MODE == 2) {
                    const __half h0 = __float2half(v0);
                    const __half h1 = __float2half(v1);
                    __half2 hp; hp.x = h0; hp.y = h1;
                    __half2 lp;
                    lp.x = __float2half(v0 - __half2float(h0));
                    lp.y = __float2half(v1 - __half2float(h1));
                    *(__half2*)(out_hi + (size_t)gr * DQ + gc) = hp;
                    *(__half2*)(out_lo + (size_t)gr * DQ + gc) = lp;
                } else if (MODE == 3) {
                    const size_t o = (size_t)z * NQ * NQ + (size_t)gr * NQ + gc;
                    const int2 ad = *(const int2*)(adj + o);
                    float2 ov;
                    ov.x = ad.x ? v0 : -1e30f;
                    ov.y = ad.y ? v1 : -1e30f;
                    *(float2*)(outf + o) = ov;
                } else {
                    const size_t o = (size_t)z * NQ * DQ + (size_t)gr * DQ + gc;
                    float2 ov;
                    ov.x = (v0 > 0.f) ? v0 : expm1f(v0);
                    ov.y = (v1 > 0.f) ? v1 : expm1f(v1);
                    *(float2*)(outf + o) = ov;
                }
            }
        }
    }
}

#define SMEM_G3P (3 * (16384 + 16384))   // MODE 1/2/3: 98304
#define SMEM_G4  (3 * (8192 + 16384))    // MODE 4: 73728

// ---------------------------------------------------------------------------
// fp32 -> fp16 hi/lo split (elementwise)
// ---------------------------------------------------------------------------
__global__ __launch_bounds__(256) void k_split(
    const float* __restrict__ in, __half* __restrict__ hi,
    __half* __restrict__ lo, int n)
{
    for (int i = blockIdx.x * 256 + threadIdx.x; i < n; i += gridDim.x * 256) {
        const float v = in[i];
        const __half h = __float2half(v);
        hi[i] = h;
        lo[i] = __float2half(v - __half2float(h));
    }
}

// attn [K,N] fp32 -> attn^T [N,K] fp16 hi/lo
__global__ __launch_bounds__(256) void k_split_T(
    const float* __restrict__ in, __half* __restrict__ hi,
    __half* __restrict__ lo)
{
    for (int i = blockIdx.x * 256 + threadIdx.x; i < DQ * DQ; i += gridDim.x * 256) {
        const int n = i / DQ, k = i % DQ;
        const float v = in[(size_t)k * DQ + n];
        const __half h = __float2half(v);
        hi[i] = h;
        lo[i] = __float2half(v - __half2float(h));
    }
}

// h [b,n,d] fp16 -> hT [b,d,n] fp16 (hi and lo)
__global__ __launch_bounds__(256) void k_transpose(
    const __half* __restrict__ hi, const __half* __restrict__ lo,
    __half* __restrict__ thi, __half* __restrict__ tlo)
{
    __shared__ __half t0[32][33], t1[32][33];
    const int b = blockIdx.z;
    const int n0 = blockIdx.x * 32, d0 = blockIdx.y * 32;
    const int tx = threadIdx.x & 31, ty = threadIdx.x >> 5;   // 32 x 8
#pragma unroll
    for (int j = 0; j < 32; j += 8) {
        const size_t idx = ((size_t)b * NQ + n0 + ty + j) * DQ + d0 + tx;
        t0[ty + j][tx] = hi[idx];
        t1[ty + j][tx] = lo[idx];
    }
    __syncthreads();
#pragma unroll
    for (int j = 0; j < 32; j += 8) {
        const size_t o = ((size_t)b * DQ + d0 + ty + j) * NQ + n0 + tx;
        thi[o] = t0[tx][ty + j];
        tlo[o] = t1[tx][ty + j];
    }
}

// ---------------------------------------------------------------------------
// Row softmax over scores -> P fp16 (single array; P in [0,1])
// ---------------------------------------------------------------------------
__global__ __launch_bounds__(256) void k_softmax(
    const float* __restrict__ S, __half* __restrict__ P)
{
    __shared__ float red[256];
    const size_t base = (size_t)blockIdx.x * NQ;
    const int tid = threadIdx.x;

    float v[8];
    float m = -INFINITY;
#pragma unroll
    for (int i = 0; i < 8; ++i) {
        v[i] = S[base + tid + i * 256];
        m = fmaxf(m, v[i]);
    }
    red[tid] = m;
    __syncthreads();
    for (int s = 128; s > 0; s >>= 1) {
        if (tid < s) red[tid] = fmaxf(red[tid], red[tid + s]);
        __syncthreads();
    }
    m = red[0];
    __syncthreads();

    float sum = 0.f;
#pragma unroll
    for (int i = 0; i < 8; ++i) {
        v[i] = expf(v[i] - m);
        sum += v[i];
    }
    red[tid] = sum;
    __syncthreads();
    for (int s = 128; s > 0; s >>= 1) {
        if (tid < s) red[tid] += red[tid + s];
        __syncthreads();
    }
    const float inv = 1.f / red[0];
#pragma unroll
    for (int i = 0; i < 8; ++i)
        P[base + tid + i * 256] = __float2half(v[i] * inv);
}

// ---------------------------------------------------------------------------
// Launch
// ---------------------------------------------------------------------------
extern "C" void kernel_launch(void* const* d_in, const int* in_sizes, int n_in,
                              void* d_out, int out_size)
{
    const float* x    = (const float*)d_in[0];
    const int*   adj  = (const int*)  d_in[1];
    const float* W    = (const float*)d_in[2];
    const float* bias = (const float*)d_in[3];
    const float* attn = (const float*)d_in[4];
    float* out = (float*)d_out;

    __half *x_hi, *x_lo, *w_hi, *w_lo, *at_hi, *at_lo;
    __half *h_hi, *h_lo, *ht_hi, *ht_lo, *ha_hi, *ha_lo, *p;
    float* s;
    cudaGetSymbolAddress((void**)&x_hi,  g_x_hi);  cudaGetSymbolAddress((void**)&x_lo,  g_x_lo);
    cudaGetSymbolAddress((void**)&w_hi,  g_w_hi);  cudaGetSymbolAddress((void**)&w_lo,  g_w_lo);
    cudaGetSymbolAddress((void**)&at_hi, g_at_hi); cudaGetSymbolAddress((void**)&at_lo, g_at_lo);
    cudaGetSymbolAddress((void**)&h_hi,  g_h_hi);  cudaGetSymbolAddress((void**)&h_lo,  g_h_lo);
    cudaGetSymbolAddress((void**)&ht_hi, g_ht_hi); cudaGetSymbolAddress((void**)&ht_lo, g_ht_lo);
    cudaGetSymbolAddress((void**)&ha_hi, g_ha_hi); cudaGetSymbolAddress((void**)&ha_lo, g_ha_lo);
    cudaGetSymbolAddress((void**)&p,     g_p);
    cudaGetSymbolAddress((void**)&s,     g_s);

    cudaFuncSetAttribute(k_mma<1>, cudaFuncAttributeMaxDynamicSharedMemorySize, SMEM_G3P);
    cudaFuncSetAttribute(k_mma<2>, cudaFuncAttributeMaxDynamicSharedMemorySize, SMEM_G3P);
    cudaFuncSetAttribute(k_mma<3>, cudaFuncAttributeMaxDynamicSharedMemorySize, SMEM_G3P);
    cudaFuncSetAttribute(k_mma<4>, cudaFuncAttributeMaxDynamicSharedMemorySize, SMEM_G4);

    // Input splits
    k_split<<<4096, 256>>>(x, x_hi, x_lo, MTOT * DQ);
    k_split<<<512, 256>>>(W, w_hi, w_lo, DQ * DQ);
    k_split_T<<<512, 256>>>(attn, at_hi, at_lo);

    // h = x @ W^T + b  (3-pass)
    k_mma<1><<<dim3(DQ / 128, MTOT / 128, 1), 128, SMEM_G3P>>>(
        x_hi, x_lo, w_hi, w_lo, bias, nullptr, nullptr, h_hi, h_lo);

    // hT per batch
    k_transpose<<<dim3(NQ / 32, DQ / 32, BQ), 256>>>(h_hi, h_lo, ht_hi, ht_lo);

    // ha = h @ attn  (3-pass)
    k_mma<2><<<dim3(DQ / 128, MTOT / 128, 1), 128, SMEM_G3P>>>(
        h_hi, h_lo, at_hi, at_lo, nullptr, nullptr, nullptr, ha_hi, ha_lo);

    // scores = ha @ h^T (per batch), adjacency-masked  (3-pass)
    k_mma<3><<<dim3(NQ / 128, NQ / 128, BQ), 128, SMEM_G3P>>>(
        ha_hi, ha_lo, h_hi, h_lo, nullptr, adj, s, nullptr, nullptr);

    // softmax rows -> P fp16
    k_softmax<<<BQ * NQ, 256>>>(s, p);

    // out = elu(P @ h) per batch  (2-pass: P single fp16, h^T split)
    k_mma<4><<<dim3(DQ / 128, NQ / 128, BQ), 128, SMEM_G4>>>(
        p, p, ht_hi, ht_lo, nullptr, nullptr, out, nullptr, nullptr);
}

// round 9
// speedup vs baseline: 1.2998x; 1.1103x over previous
#include <cuda_runtime.h>
#include <cuda_fp16.h>
#include <cstdint>
#include <math.h>

// ---------------------------------------------------------------------------
// Problem constants
// ---------------------------------------------------------------------------
#define BQ 8
#define NQ 2048
#define DQ 512
#define MTOT (BQ * NQ)   // 16384

// ---------------------------------------------------------------------------
// Device scratch (no runtime allocation allowed)
// ---------------------------------------------------------------------------
__device__ __half g_x_hi[MTOT * DQ], g_x_lo[MTOT * DQ];
__device__ __half g_w_hi[DQ * DQ],   g_w_lo[DQ * DQ];
__device__ __half g_at_hi[DQ * DQ],  g_at_lo[DQ * DQ];     // attn^T
__device__ __half g_h_hi[MTOT * DQ],  g_h_lo[MTOT * DQ];
__device__ __half g_ht_hi[MTOT * DQ];                      // per-batch H^T (hi only)
__device__ __half g_ha_hi[MTOT * DQ], g_ha_lo[MTOT * DQ];
__device__ __half g_p[(size_t)BQ * NQ * NQ];               // softmax weights, fp16
__device__ float g_s[(size_t)BQ * NQ * NQ];

// ---------------------------------------------------------------------------
// Low-level helpers (base compute_103 features only)
// ---------------------------------------------------------------------------
__device__ __forceinline__ uint32_t smem_u32(const void* p) {
    uint32_t a;
    asm("{ .reg .u64 t; cvta.to.shared.u64 t, %1; cvt.u32.u64 %0, t; }" : "=r"(a) : "l"(p));
    return a;
}

#define CP16(dst, src) \
    asm volatile("cp.async.cg.shared.global [%0], [%1], 16;\n" :: "r"(dst), "l"(src) : "memory")
#define CP_COMMIT() asm volatile("cp.async.commit_group;\n" ::: "memory")
#define CP_WAIT1()  asm volatile("cp.async.wait_group 1;\n" ::: "memory")

__device__ __forceinline__ void ldsm4(uint32_t* r, uint32_t addr) {
    asm volatile("ldmatrix.sync.aligned.m8n8.x4.shared.b16 {%0,%1,%2,%3}, [%4];\n"
                 : "=r"(r[0]), "=r"(r[1]), "=r"(r[2]), "=r"(r[3]) : "r"(addr));
}

__device__ __forceinline__ void mma16816(float* c, const uint32_t* a, const uint32_t* b) {
    asm volatile(
        "mma.sync.aligned.m16n8k16.row.col.f32.f16.f16.f32 "
        "{%0,%1,%2,%3}, {%4,%5,%6,%7}, {%8,%9}, {%0,%1,%2,%3};\n"
        : "+f"(c[0]), "+f"(c[1]), "+f"(c[2]), "+f"(c[3])
        : "r"(a[0]), "r"(a[1]), "r"(a[2]), "r"(a[3]), "r"(b[0]), "r"(b[1]));
}

// ---------------------------------------------------------------------------
// Unified HMMA GEMM: C[m,n] = sum_k A[m,k] * B[n,k] via fp16 split
// CTA tile 128x128, 128 threads = 4 warps (2 along M x 2 along N), warp 64x64.
// MODE 1: 3-pass, out = C + bias -> h hi/lo + fused hT_hi   (M=16384,N=512,K=512)
// MODE 2: 3-pass, out = C        -> ha hi/lo                 (M=16384,N=512,K=512)
// MODE 3: 3-pass, out = mask(C)  -> scores fp32   (per batch, M=N=2048, K=512)
// MODE 4: 1-pass (A = P fp16, B = hT_hi fp16), out = elu(C) -> fp32
//         (per batch, M=2048, N=512, K=2048)
// SMEM swizzles: 128B rows phys = row*128 + (off ^ ((row&7)<<4));
//                64B rows phys = row*64 + (off ^ ((row&3)<<4)).
// ---------------------------------------------------------------------------
template <int MODE>
__global__ __launch_bounds__(128, 2) void k_mma(
    const __half* __restrict__ Ahi, const __half* __restrict__ Alo,
    const __half* __restrict__ Bhi, const __half* __restrict__ Blo,
    const float* __restrict__ bias, const int* __restrict__ adj,
    float* __restrict__ outf,
    __half* __restrict__ out_hi, __half* __restrict__ out_lo,
    __half* __restrict__ out_t)
{
    constexpr bool SPL  = (MODE != 4);         // split (hi/lo) operands?
    constexpr int KDIM = (MODE == 4) ? 2048 : 512;
    constexpr int LDA  = (MODE == 4) ? 2048 : 512;
    constexpr int LDB  = (MODE == 4) ? 2048 : 512;
    constexpr int NST  = KDIM / 32;
    constexpr int ASB  = SPL ? 16384 : 8192;   // A tile bytes
    constexpr int BSB  = SPL ? 16384 : 8192;   // B tile bytes
    constexpr int STG  = ASB + BSB;            // stage bytes

    extern __shared__ char smem[];
    const uint32_t sbase = smem_u32(smem);
    const int tid = threadIdx.x;
    const int lane = tid & 31, wid = tid >> 5;
    const int warp_m = wid & 1;        // 2 warps along M (64 rows each)
    const int warp_n = wid >> 1;       // 2 warps along N (64 cols each)

    const int bn = blockIdx.x * 128, bm = blockIdx.y * 128, z = blockIdx.z;
    size_t aoff = 0, boff = 0;
    if (MODE == 3) { aoff = (size_t)z * NQ * DQ; boff = (size_t)z * NQ * DQ; }
    if (MODE == 4) { aoff = (size_t)z * NQ * NQ; boff = (size_t)z * DQ * NQ; }

    const char* A0h = (const char*)(Ahi + aoff + (size_t)bm * LDA);
    const char* A0l = (const char*)(Alo + aoff + (size_t)bm * LDA);
    const char* B0h = (const char*)(Bhi + boff + (size_t)bn * LDB);
    const char* B0l = (const char*)(Blo + boff + (size_t)bn * LDB);

    auto issue_stage = [&](uint32_t sd, int kb) {
        if (SPL) {
            const uint32_t row0 = tid >> 3;
            const uint32_t c = tid & 7;
            const uint32_t off = c * 16;
            const char* srcA = (c < 4) ? A0h : A0l;
            const char* srcB = (c < 4) ? B0h : B0l;
            const int cb = (c & 3) * 16;
#pragma unroll
            for (int blk = 0; blk < 8; ++blk) {
                const uint32_t row = row0 + blk * 16;
                const uint32_t sw = row * 128 + (off ^ ((row & 7) << 4));
                CP16(sd + sw,       srcA + (size_t)row * (LDA * 2) + kb + cb);
                CP16(sd + ASB + sw, srcB + (size_t)row * (LDB * 2) + kb + cb);
            }
        } else {
            const uint32_t row0 = tid >> 2;
            const uint32_t c = tid & 3;
            const uint32_t off = c * 16;
#pragma unroll
            for (int blk = 0; blk < 4; ++blk) {
                const uint32_t row = row0 + blk * 32;
                const uint32_t sw = row * 64 + (off ^ ((row & 3) << 4));
                CP16(sd + sw,       A0h + (size_t)row * (LDA * 2) + kb + c * 16);
                CP16(sd + ASB + sw, B0h + (size_t)row * (LDB * 2) + kb + c * 16);
            }
        }
    };

    // per-lane ldmatrix row bases (A: 4 m16 tiles, B: 4 n16 groups)
    uint32_t a_rt[4], a_sw[4];
#pragma unroll
    for (int mi = 0; mi < 4; ++mi) {
        const uint32_t r = warp_m * 64 + mi * 16 + (lane & 15);
        if (SPL) { a_rt[mi] = r * 128; a_sw[mi] = (r & 7) << 4; }
        else     { a_rt[mi] = r * 64;  a_sw[mi] = (r & 3) << 4; }
    }
    uint32_t b_rt[4], b_sw[4];
    {
        const uint32_t brow = (lane & 7) + ((lane >> 4) & 1) * 8;
#pragma unroll
        for (int jp = 0; jp < 4; ++jp) {
            const uint32_t r = warp_n * 64 + jp * 16 + brow;
            if (SPL) { b_rt[jp] = r * 128; b_sw[jp] = (r & 7) << 4; }
            else     { b_rt[jp] = r * 64;  b_sw[jp] = (r & 3) << 4; }
        }
    }
    const uint32_t a_koff = (lane >> 4) * 16;        // 0 or 16
    const uint32_t b_koff = ((lane >> 3) & 1) * 16;  // 0 or 16

    float acc[4][8][4];
#pragma unroll
    for (int i = 0; i < 4; ++i)
#pragma unroll
        for (int j = 0; j < 8; ++j)
#pragma unroll
            for (int k = 0; k < 4; ++k) acc[i][j][k] = 0.f;

    // prologue: stages 0, 1
    issue_stage(sbase, 0);
    CP_COMMIT();
    issue_stage(sbase + STG, 64);
    CP_COMMIT();

    int buf = 0, nbuf = 2;
    for (int i = 0; i < NST; ++i) {
        CP_WAIT1();
        __syncthreads();
        if (i + 2 < NST)
            issue_stage(sbase + nbuf * STG, (i + 2) * 64);
        CP_COMMIT();   // empty group when not issuing keeps wait_group 1 exact

        const uint32_t sa = sbase + buf * STG;
        const uint32_t sb = sa + ASB;
#pragma unroll
        for (int ks = 0; ks < 2; ++ks) {
            const uint32_t ko = ks * 32;
            uint32_t ah[4][4], al[4][4];
#pragma unroll
            for (int mi = 0; mi < 4; ++mi) {
                ldsm4(ah[mi], sa + a_rt[mi] + ((ko + a_koff)      ^ a_sw[mi]));
                if (SPL)
                    ldsm4(al[mi], sa + a_rt[mi] + ((ko + a_koff + 64) ^ a_sw[mi]));
            }
#pragma unroll
            for (int jp = 0; jp < 4; ++jp) {
                uint32_t bh[4], bl[4];
                ldsm4(bh, sb + b_rt[jp] + ((ko + b_koff) ^ b_sw[jp]));
                if (SPL)
                    ldsm4(bl, sb + b_rt[jp] + ((ko + b_koff + 64) ^ b_sw[jp]));
#pragma unroll
                for (int mi = 0; mi < 4; ++mi) {
                    mma16816(acc[mi][2*jp],   ah[mi], bh);
                    if (SPL) {
                        mma16816(acc[mi][2*jp], ah[mi], bl);
                        mma16816(acc[mi][2*jp], al[mi], bh);
                    }
                    mma16816(acc[mi][2*jp+1], ah[mi], bh + 2);
                    if (SPL) {
                        mma16816(acc[mi][2*jp+1], ah[mi], bl + 2);
                        mma16816(acc[mi][2*jp+1], al[mi], bh + 2);
                    }
                }
            }
        }
        buf = (buf == 2) ? 0 : buf + 1;
        nbuf = (nbuf == 2) ? 0 : nbuf + 1;
    }

    // -----------------------------------------------------------------------
    // Epilogue
    // -----------------------------------------------------------------------
    const int rbase = bm + warp_m * 64 + (lane >> 2);
    const int cbase = bn + warp_n * 64 + (lane & 3) * 2;

    // For MODE 1: stage hi values into smem for the fused transpose.
    __half* st = (__half*)(smem + STG);   // [128 d][136 n] fp16; stages 1,2 stale
    if (MODE == 1) __syncthreads();       // all MMA reads of stage smem done

#pragma unroll
    for (int mi = 0; mi < 4; ++mi) {
#pragma unroll
        for (int j = 0; j < 8; ++j) {
            const int gc = cbase + j * 8;
#pragma unroll
            for (int half = 0; half < 2; ++half) {
                const int gr = rbase + mi * 16 + half * 8;
                float v0 = acc[mi][j][half * 2 + 0];
                float v1 = acc[mi][j][half * 2 + 1];
                if (MODE == 1) {
                    const float2 bv = *(const float2*)(bias + gc);
                    v0 += bv.x; v1 += bv.y;
                }
                if (MODE == 1 || MODE == 2) {
                    const __half h0 = __float2half(v0);
                    const __half h1 = __float2half(v1);
                    __half2 hp; hp.x = h0; hp.y = h1;
                    __half2 lp;
                    lp.x = __float2half(v0 - __half2float(h0));
                    lp.y = __float2half(v1 - __half2float(h1));
                    *(__half2*)(out_hi + (size_t)gr * DQ + gc) = hp;
                    *(__half2*)(out_lo + (size_t)gr * DQ + gc) = lp;
                    if (MODE == 1) {
                        st[(gc - bn)     * 136 + (gr - bm)] = h0;
                        st[(gc + 1 - bn) * 136 + (gr - bm)] = h1;
                    }
                } else if (MODE == 3) {
                    const size_t o = (size_t)z * NQ * NQ + (size_t)gr * NQ + gc;
                    const int2 ad = *(const int2*)(adj + o);
                    float2 ov;
                    ov.x = ad.x ? v0 : -1e30f;
                    ov.y = ad.y ? v1 : -1e30f;
                    *(float2*)(outf + o) = ov;
                } else {
                    const size_t o = (size_t)z * NQ * DQ + (size_t)gr * DQ + gc;
                    float2 ov;
                    ov.x = (v0 > 0.f) ? v0 : expm1f(v0);
                    ov.y = (v1 > 0.f) ? v1 : expm1f(v1);
                    *(float2*)(outf + o) = ov;
                }
            }
        }
    }

    if (MODE == 1) {
        __syncthreads();
        // coalesced transposed write: thread tid owns d-row (bn + tid)
        const int b = bm >> 11, n0 = bm & 2047;
        const __half* src = st + tid * 136;
        __half* dst = out_t + ((size_t)(b * DQ + bn + tid)) * NQ + n0;
#pragma unroll
        for (int k2 = 0; k2 < 16; ++k2)
            *(float4*)(dst + k2 * 8) = *(const float4*)(src + k2 * 8);
    }
}

#define SMEM_G3P (3 * 32768)             // MODE 1/2/3: 98304
#define SMEM_G4  (3 * 16384)             // MODE 4: 49152

// ---------------------------------------------------------------------------
// fp32 -> fp16 hi/lo split (elementwise)
// ---------------------------------------------------------------------------
__global__ __launch_bounds__(256) void k_split(
    const float* __restrict__ in, __half* __restrict__ hi,
    __half* __restrict__ lo, int n)
{
    for (int i = blockIdx.x * 256 + threadIdx.x; i < n; i += gridDim.x * 256) {
        const float v = in[i];
        const __half h = __float2half(v);
        hi[i] = h;
        lo[i] = __float2half(v - __half2float(h));
    }
}

// attn [K,N] fp32 -> attn^T [N,K] fp16 hi/lo
__global__ __launch_bounds__(256) void k_split_T(
    const float* __restrict__ in, __half* __restrict__ hi,
    __half* __restrict__ lo)
{
    for (int i = blockIdx.x * 256 + threadIdx.x; i < DQ * DQ; i += gridDim.x * 256) {
        const int n = i / DQ, k = i % DQ;
        const float v = in[(size_t)k * DQ + n];
        const __half h = __float2half(v);
        hi[i] = h;
        lo[i] = __float2half(v - __half2float(h));
    }
}

// ---------------------------------------------------------------------------
// Row softmax over scores -> P fp16. 512 threads, 4 elems/thread, shfl+smem.
// ---------------------------------------------------------------------------
__global__ __launch_bounds__(512) void k_softmax(
    const float* __restrict__ S, __half* __restrict__ P)
{
    __shared__ float red[16];
    const size_t base = (size_t)blockIdx.x * NQ;
    const int tid = threadIdx.x;
    const int lane = tid & 31, wid = tid >> 5;

    float4 v = *(const float4*)(S + base + tid * 4);

    float m = fmaxf(fmaxf(v.x, v.y), fmaxf(v.z, v.w));
#pragma unroll
    for (int o = 16; o > 0; o >>= 1)
        m = fmaxf(m, __shfl_xor_sync(0xffffffff, m, o));
    if (lane == 0) red[wid] = m;
    __syncthreads();
    if (wid == 0) {
        float t = red[lane & 15];
#pragma unroll
        for (int o = 8; o > 0; o >>= 1)
            t = fmaxf(t, __shfl_xor_sync(0xffffffff, t, o));
        if (lane == 0) red[0] = t;
    }
    __syncthreads();
    m = red[0];

    v.x = expf(v.x - m); v.y = expf(v.y - m);
    v.z = expf(v.z - m); v.w = expf(v.w - m);
    float s = v.x + v.y + v.z + v.w;
#pragma unroll
    for (int o = 16; o > 0; o >>= 1)
        s += __shfl_xor_sync(0xffffffff, s, o);
    __syncthreads();
    if (lane == 0) red[wid] = s;
    __syncthreads();
    if (wid == 0) {
        float t = red[lane & 15];
#pragma unroll
        for (int o = 8; o > 0; o >>= 1)
            t += __shfl_xor_sync(0xffffffff, t, o);
        if (lane == 0) red[0] = t;
    }
    __syncthreads();
    const float inv = 1.f / red[0];

    __half2 o0, o1;
    o0.x = __float2half(v.x * inv); o0.y = __float2half(v.y * inv);
    o1.x = __float2half(v.z * inv); o1.y = __float2half(v.w * inv);
    __half2* dst = (__half2*)(P + base + tid * 4);
    dst[0] = o0; dst[1] = o1;
}

// ---------------------------------------------------------------------------
// Launch
// ---------------------------------------------------------------------------
extern "C" void kernel_launch(void* const* d_in, const int* in_sizes, int n_in,
                              void* d_out, int out_size)
{
    const float* x    = (const float*)d_in[0];
    const int*   adj  = (const int*)  d_in[1];
    const float* W    = (const float*)d_in[2];
    const float* bias = (const float*)d_in[3];
    const float* attn = (const float*)d_in[4];
    float* out = (float*)d_out;

    __half *x_hi, *x_lo, *w_hi, *w_lo, *at_hi, *at_lo;
    __half *h_hi, *h_lo, *ht_hi, *ha_hi, *ha_lo, *p;
    float* s;
    cudaGetSymbolAddress((void**)&x_hi,  g_x_hi);  cudaGetSymbolAddress((void**)&x_lo,  g_x_lo);
    cudaGetSymbolAddress((void**)&w_hi,  g_w_hi);  cudaGetSymbolAddress((void**)&w_lo,  g_w_lo);
    cudaGetSymbolAddress((void**)&at_hi, g_at_hi); cudaGetSymbolAddress((void**)&at_lo, g_at_lo);
    cudaGetSymbolAddress((void**)&h_hi,  g_h_hi);  cudaGetSymbolAddress((void**)&h_lo,  g_h_lo);
    cudaGetSymbolAddress((void**)&ht_hi, g_ht_hi);
    cudaGetSymbolAddress((void**)&ha_hi, g_ha_hi); cudaGetSymbolAddress((void**)&ha_lo, g_ha_lo);
    cudaGetSymbolAddress((void**)&p,     g_p);
    cudaGetSymbolAddress((void**)&s,     g_s);

    cudaFuncSetAttribute(k_mma<1>, cudaFuncAttributeMaxDynamicSharedMemorySize, SMEM_G3P);
    cudaFuncSetAttribute(k_mma<2>, cudaFuncAttributeMaxDynamicSharedMemorySize, SMEM_G3P);
    cudaFuncSetAttribute(k_mma<3>, cudaFuncAttributeMaxDynamicSharedMemorySize, SMEM_G3P);
    cudaFuncSetAttribute(k_mma<4>, cudaFuncAttributeMaxDynamicSharedMemorySize, SMEM_G4);

    // Input splits
    k_split<<<4096, 256>>>(x, x_hi, x_lo, MTOT * DQ);
    k_split<<<512, 256>>>(W, w_hi, w_lo, DQ * DQ);
    k_split_T<<<512, 256>>>(attn, at_hi, at_lo);

    // h = x @ W^T + b  (3-pass), hT_hi produced in epilogue
    k_mma<1><<<dim3(DQ / 128, MTOT / 128, 1), 128, SMEM_G3P>>>(
        x_hi, x_lo, w_hi, w_lo, bias, nullptr, nullptr, h_hi, h_lo, ht_hi);

    // ha = h @ attn  (3-pass)
    k_mma<2><<<dim3(DQ / 128, MTOT / 128, 1), 128, SMEM_G3P>>>(
        h_hi, h_lo, at_hi, at_lo, nullptr, nullptr, nullptr, ha_hi, ha_lo, nullptr);

    // scores = ha @ h^T (per batch), adjacency-masked  (3-pass)
    k_mma<3><<<dim3(NQ / 128, NQ / 128, BQ), 128, SMEM_G3P>>>(
        ha_hi, ha_lo, h_hi, h_lo, nullptr, adj, s, nullptr, nullptr, nullptr);

    // softmax rows -> P fp16
    k_softmax<<<BQ * NQ, 512>>>(s, p);

    // out = elu(P @ h) per batch  (1-pass: P fp16, hT_hi fp16)
    k_mma<4><<<dim3(DQ / 128, NQ / 128, BQ), 128, SMEM_G4>>>(
        p, p, ht_hi, ht_hi, nullptr, nullptr, out, nullptr, nullptr, nullptr);
}

// round 10
// speedup vs baseline: 1.3056x; 1.0045x over previous
#include <cuda_runtime.h>
#include <cuda_fp16.h>
#include <cstdint>
#include <math.h>

// ---------------------------------------------------------------------------
// Problem constants
// ---------------------------------------------------------------------------
#define BQ 8
#define NQ 2048
#define DQ 512
#define MTOT (BQ * NQ)   // 16384

// ---------------------------------------------------------------------------
// Device scratch (no runtime allocation allowed)
// ---------------------------------------------------------------------------
__device__ __half g_x_hi[MTOT * DQ], g_x_lo[MTOT * DQ];
__device__ __half g_w_hi[DQ * DQ],   g_w_lo[DQ * DQ];
__device__ __half g_at_hi[DQ * DQ],  g_at_lo[DQ * DQ];     // attn^T
__device__ __half g_h_hi[MTOT * DQ],  g_h_lo[MTOT * DQ];
__device__ __half g_ht_hi[MTOT * DQ];                      // per-batch H^T (hi only)
__device__ __half g_ha_hi[MTOT * DQ], g_ha_lo[MTOT * DQ];
__device__ __half g_p[(size_t)BQ * NQ * NQ];               // softmax weights, fp16
__device__ float g_s[(size_t)BQ * NQ * NQ];

// ---------------------------------------------------------------------------
// Low-level helpers (base compute_103 features only)
// ---------------------------------------------------------------------------
__device__ __forceinline__ uint32_t smem_u32(const void* p) {
    uint32_t a;
    asm("{ .reg .u64 t; cvta.to.shared.u64 t, %1; cvt.u32.u64 %0, t; }" : "=r"(a) : "l"(p));
    return a;
}

#define CP16(dst, src) \
    asm volatile("cp.async.cg.shared.global [%0], [%1], 16;\n" :: "r"(dst), "l"(src) : "memory")
#define CP_COMMIT() asm volatile("cp.async.commit_group;\n" ::: "memory")
#define CP_WAIT1()  asm volatile("cp.async.wait_group 1;\n" ::: "memory")

__device__ __forceinline__ void ldsm4(uint32_t* r, uint32_t addr) {
    asm volatile("ldmatrix.sync.aligned.m8n8.x4.shared.b16 {%0,%1,%2,%3}, [%4];\n"
                 : "=r"(r[0]), "=r"(r[1]), "=r"(r[2]), "=r"(r[3]) : "r"(addr));
}

__device__ __forceinline__ void mma16816(float* c, const uint32_t* a, const uint32_t* b) {
    asm volatile(
        "mma.sync.aligned.m16n8k16.row.col.f32.f16.f16.f32 "
        "{%0,%1,%2,%3}, {%4,%5,%6,%7}, {%8,%9}, {%0,%1,%2,%3};\n"
        : "+f"(c[0]), "+f"(c[1]), "+f"(c[2]), "+f"(c[3])
        : "r"(a[0]), "r"(a[1]), "r"(a[2]), "r"(a[3]), "r"(b[0]), "r"(b[1]));
}

// ---------------------------------------------------------------------------
// Unified HMMA GEMM: C[m,n] = sum_k A[m,k] * B[n,k] via fp16 split
// CTA tile 128x128, 128 threads = 4 warps (2 along M x 2 along N), warp 64x64.
// Inner loop is PASS-MAJOR: all 16 hh MMAs (distinct accumulators), then all
// hl, then all lh -- same-accumulator reuse distance 16 instructions, so the
// HMMA C-operand RAW latency is fully hidden. Per-accumulator accumulation
// order (hh, hl, lh per k16) is unchanged vs previous rounds (bit-identical).
// MODE 1: 3-pass, out = C + bias -> h hi/lo + fused hT_hi   (M=16384,N=512,K=512)
// MODE 2: 3-pass, out = C        -> ha hi/lo                 (M=16384,N=512,K=512)
// MODE 3: 3-pass, out = mask(C)  -> scores fp32   (per batch, M=N=2048, K=512)
// MODE 4: 1-pass (A = P fp16, B = hT_hi fp16), out = elu(C) -> fp32
//         (per batch, M=2048, N=512, K=2048)
// SMEM swizzles: 128B rows phys = row*128 + (off ^ ((row&7)<<4));
//                64B rows phys = row*64 + (off ^ ((row&3)<<4)).
// ---------------------------------------------------------------------------
template <int MODE>
__global__ __launch_bounds__(128, 2) void k_mma(
    const __half* __restrict__ Ahi, const __half* __restrict__ Alo,
    const __half* __restrict__ Bhi, const __half* __restrict__ Blo,
    const float* __restrict__ bias, const int* __restrict__ adj,
    float* __restrict__ outf,
    __half* __restrict__ out_hi, __half* __restrict__ out_lo,
    __half* __restrict__ out_t)
{
    constexpr bool SPL  = (MODE != 4);         // split (hi/lo) operands?
    constexpr int KDIM = (MODE == 4) ? 2048 : 512;
    constexpr int LDA  = (MODE == 4) ? 2048 : 512;
    constexpr int LDB  = (MODE == 4) ? 2048 : 512;
    constexpr int NST  = KDIM / 32;
    constexpr int ASB  = SPL ? 16384 : 8192;   // A tile bytes
    constexpr int BSB  = SPL ? 16384 : 8192;   // B tile bytes
    constexpr int STG  = ASB + BSB;            // stage bytes

    extern __shared__ char smem[];
    const uint32_t sbase = smem_u32(smem);
    const int tid = threadIdx.x;
    const int lane = tid & 31, wid = tid >> 5;
    const int warp_m = wid & 1;        // 2 warps along M (64 rows each)
    const int warp_n = wid >> 1;       // 2 warps along N (64 cols each)

    const int bn = blockIdx.x * 128, bm = blockIdx.y * 128, z = blockIdx.z;
    size_t aoff = 0, boff = 0;
    if (MODE == 3) { aoff = (size_t)z * NQ * DQ; boff = (size_t)z * NQ * DQ; }
    if (MODE == 4) { aoff = (size_t)z * NQ * NQ; boff = (size_t)z * DQ * NQ; }

    const char* A0h = (const char*)(Ahi + aoff + (size_t)bm * LDA);
    const char* A0l = (const char*)(Alo + aoff + (size_t)bm * LDA);
    const char* B0h = (const char*)(Bhi + boff + (size_t)bn * LDB);
    const char* B0l = (const char*)(Blo + boff + (size_t)bn * LDB);

    auto issue_stage = [&](uint32_t sd, int kb) {
        if (SPL) {
            const uint32_t row0 = tid >> 3;
            const uint32_t c = tid & 7;
            const uint32_t off = c * 16;
            const char* srcA = (c < 4) ? A0h : A0l;
            const char* srcB = (c < 4) ? B0h : B0l;
            const int cb = (c & 3) * 16;
#pragma unroll
            for (int blk = 0; blk < 8; ++blk) {
                const uint32_t row = row0 + blk * 16;
                const uint32_t sw = row * 128 + (off ^ ((row & 7) << 4));
                CP16(sd + sw,       srcA + (size_t)row * (LDA * 2) + kb + cb);
                CP16(sd + ASB + sw, srcB + (size_t)row * (LDB * 2) + kb + cb);
            }
        } else {
            const uint32_t row0 = tid >> 2;
            const uint32_t c = tid & 3;
            const uint32_t off = c * 16;
#pragma unroll
            for (int blk = 0; blk < 4; ++blk) {
                const uint32_t row = row0 + blk * 32;
                const uint32_t sw = row * 64 + (off ^ ((row & 3) << 4));
                CP16(sd + sw,       A0h + (size_t)row * (LDA * 2) + kb + c * 16);
                CP16(sd + ASB + sw, B0h + (size_t)row * (LDB * 2) + kb + c * 16);
            }
        }
    };

    // per-lane ldmatrix row bases (A: 4 m16 tiles, B: 4 n16 groups)
    uint32_t a_rt[4], a_sw[4];
#pragma unroll
    for (int mi = 0; mi < 4; ++mi) {
        const uint32_t r = warp_m * 64 + mi * 16 + (lane & 15);
        if (SPL) { a_rt[mi] = r * 128; a_sw[mi] = (r & 7) << 4; }
        else     { a_rt[mi] = r * 64;  a_sw[mi] = (r & 3) << 4; }
    }
    uint32_t b_rt[4], b_sw[4];
    {
        const uint32_t brow = (lane & 7) + ((lane >> 4) & 1) * 8;
#pragma unroll
        for (int jp = 0; jp < 4; ++jp) {
            const uint32_t r = warp_n * 64 + jp * 16 + brow;
            if (SPL) { b_rt[jp] = r * 128; b_sw[jp] = (r & 7) << 4; }
            else     { b_rt[jp] = r * 64;  b_sw[jp] = (r & 3) << 4; }
        }
    }
    const uint32_t a_koff = (lane >> 4) * 16;        // 0 or 16
    const uint32_t b_koff = ((lane >> 3) & 1) * 16;  // 0 or 16

    float acc[4][8][4];
#pragma unroll
    for (int i = 0; i < 4; ++i)
#pragma unroll
        for (int j = 0; j < 8; ++j)
#pragma unroll
            for (int k = 0; k < 4; ++k) acc[i][j][k] = 0.f;

    // prologue: stages 0, 1
    issue_stage(sbase, 0);
    CP_COMMIT();
    issue_stage(sbase + STG, 64);
    CP_COMMIT();

    int buf = 0, nbuf = 2;
    for (int i = 0; i < NST; ++i) {
        CP_WAIT1();
        __syncthreads();
        if (i + 2 < NST)
            issue_stage(sbase + nbuf * STG, (i + 2) * 64);
        CP_COMMIT();   // empty group when not issuing keeps wait_group 1 exact

        const uint32_t sa = sbase + buf * STG;
        const uint32_t sb = sa + ASB;
#pragma unroll
        for (int ks = 0; ks < 2; ++ks) {
            const uint32_t ko = ks * 32;
            uint32_t ah[4][4], al[4][4], bh[4][4], bl[4][4];
#pragma unroll
            for (int mi = 0; mi < 4; ++mi) {
                ldsm4(ah[mi], sa + a_rt[mi] + ((ko + a_koff) ^ a_sw[mi]));
                if (SPL)
                    ldsm4(al[mi], sa + a_rt[mi] + ((ko + a_koff + 64) ^ a_sw[mi]));
            }
#pragma unroll
            for (int jp = 0; jp < 4; ++jp) {
                ldsm4(bh[jp], sb + b_rt[jp] + ((ko + b_koff) ^ b_sw[jp]));
                if (SPL)
                    ldsm4(bl[jp], sb + b_rt[jp] + ((ko + b_koff + 64) ^ b_sw[jp]));
            }
            // pass 1: hi*hi (16 independent accumulators back-to-back)
#pragma unroll
            for (int mi = 0; mi < 4; ++mi)
#pragma unroll
                for (int jp = 0; jp < 4; ++jp) {
                    mma16816(acc[mi][2*jp],   ah[mi], bh[jp]);
                    mma16816(acc[mi][2*jp+1], ah[mi], bh[jp] + 2);
                }
            if (SPL) {
                // pass 2: hi*lo
#pragma unroll
                for (int mi = 0; mi < 4; ++mi)
#pragma unroll
                    for (int jp = 0; jp < 4; ++jp) {
                        mma16816(acc[mi][2*jp],   ah[mi], bl[jp]);
                        mma16816(acc[mi][2*jp+1], ah[mi], bl[jp] + 2);
                    }
                // pass 3: lo*hi
#pragma unroll
                for (int mi = 0; mi < 4; ++mi)
#pragma unroll
                    for (int jp = 0; jp < 4; ++jp) {
                        mma16816(acc[mi][2*jp],   al[mi], bh[jp]);
                        mma16816(acc[mi][2*jp+1], al[mi], bh[jp] + 2);
                    }
            }
        }
        buf = (buf == 2) ? 0 : buf + 1;
        nbuf = (nbuf == 2) ? 0 : nbuf + 1;
    }

    // -----------------------------------------------------------------------
    // Epilogue
    // -----------------------------------------------------------------------
    const int rbase = bm + warp_m * 64 + (lane >> 2);
    const int cbase = bn + warp_n * 64 + (lane & 3) * 2;

    // For MODE 1: stage hi values into smem for the fused transpose.
    __half* st = (__half*)(smem + STG);   // [128 d][136 n] fp16; stages 1,2 stale
    if (MODE == 1) __syncthreads();       // all MMA reads of stage smem done

#pragma unroll
    for (int mi = 0; mi < 4; ++mi) {
#pragma unroll
        for (int j = 0; j < 8; ++j) {
            const int gc = cbase + j * 8;
#pragma unroll
            for (int half = 0; half < 2; ++half) {
                const int gr = rbase + mi * 16 + half * 8;
                float v0 = acc[mi][j][half * 2 + 0];
                float v1 = acc[mi][j][half * 2 + 1];
                if (MODE == 1) {
                    const float2 bv = *(const float2*)(bias + gc);
                    v0 += bv.x; v1 += bv.y;
                }
                if (MODE == 1 || MODE == 2) {
                    const __half h0 = __float2half(v0);
                    const __half h1 = __float2half(v1);
                    __half2 hp; hp.x = h0; hp.y = h1;
                    __half2 lp;
                    lp.x = __float2half(v0 - __half2float(h0));
                    lp.y = __float2half(v1 - __half2float(h1));
                    *(__half2*)(out_hi + (size_t)gr * DQ + gc) = hp;
                    *(__half2*)(out_lo + (size_t)gr * DQ + gc) = lp;
                    if (MODE == 1) {
                        st[(gc - bn)     * 136 + (gr - bm)] = h0;
                        st[(gc + 1 - bn) * 136 + (gr - bm)] = h1;
                    }
                } else if (MODE == 3) {
                    const size_t o = (size_t)z * NQ * NQ + (size_t)gr * NQ + gc;
                    const int2 ad = *(const int2*)(adj + o);
                    float2 ov;
                    ov.x = ad.x ? v0 : -1e30f;
                    ov.y = ad.y ? v1 : -1e30f;
                    *(float2*)(outf + o) = ov;
                } else {
                    const size_t o = (size_t)z * NQ * DQ + (size_t)gr * DQ + gc;
                    float2 ov;
                    ov.x = (v0 > 0.f) ? v0 : expm1f(v0);
                    ov.y = (v1 > 0.f) ? v1 : expm1f(v1);
                    *(float2*)(outf + o) = ov;
                }
            }
        }
    }

    if (MODE == 1) {
        __syncthreads();
        // coalesced transposed write: thread tid owns d-row (bn + tid)
        const int b = bm >> 11, n0 = bm & 2047;
        const __half* src = st + tid * 136;
        __half* dst = out_t + ((size_t)(b * DQ + bn + tid)) * NQ + n0;
#pragma unroll
        for (int k2 = 0; k2 < 16; ++k2)
            *(float4*)(dst + k2 * 8) = *(const float4*)(src + k2 * 8);
    }
}

#define SMEM_G3P (3 * 32768)             // MODE 1/2/3: 98304
#define SMEM_G4  (3 * 16384)             // MODE 4: 49152

// ---------------------------------------------------------------------------
// fp32 -> fp16 hi/lo split (elementwise)
// ---------------------------------------------------------------------------
__global__ __launch_bounds__(256) void k_split(
    const float* __restrict__ in, __half* __restrict__ hi,
    __half* __restrict__ lo, int n)
{
    for (int i = blockIdx.x * 256 + threadIdx.x; i < n; i += gridDim.x * 256) {
        const float v = in[i];
        const __half h = __float2half(v);
        hi[i] = h;
        lo[i] = __float2half(v - __half2float(h));
    }
}

// attn [K,N] fp32 -> attn^T [N,K] fp16 hi/lo
__global__ __launch_bounds__(256) void k_split_T(
    const float* __restrict__ in, __half* __restrict__ hi,
    __half* __restrict__ lo)
{
    for (int i = blockIdx.x * 256 + threadIdx.x; i < DQ * DQ; i += gridDim.x * 256) {
        const int n = i / DQ, k = i % DQ;
        const float v = in[(size_t)k * DQ + n];
        const __half h = __float2half(v);
        hi[i] = h;
        lo[i] = __float2half(v - __half2float(h));
    }
}

// ---------------------------------------------------------------------------
// Row softmax over scores -> P fp16. 512 threads, 4 elems/thread, shfl+smem.
// ---------------------------------------------------------------------------
__global__ __launch_bounds__(512) void k_softmax(
    const float* __restrict__ S, __half* __restrict__ P)
{
    __shared__ float red[16];
    const size_t base = (size_t)blockIdx.x * NQ;
    const int tid = threadIdx.x;
    const int lane = tid & 31, wid = tid >> 5;

    float4 v = *(const float4*)(S + base + tid * 4);

    float m = fmaxf(fmaxf(v.x, v.y), fmaxf(v.z, v.w));
#pragma unroll
    for (int o = 16; o > 0; o >>= 1)
        m = fmaxf(m, __shfl_xor_sync(0xffffffff, m, o));
    if (lane == 0) red[wid] = m;
    __syncthreads();
    if (wid == 0) {
        float t = red[lane & 15];
#pragma unroll
        for (int o = 8; o > 0; o >>= 1)
            t = fmaxf(t, __shfl_xor_sync(0xffffffff, t, o));
        if (lane == 0) red[0] = t;
    }
    __syncthreads();
    m = red[0];

    v.x = expf(v.x - m); v.y = expf(v.y - m);
    v.z = expf(v.z - m); v.w = expf(v.w - m);
    float s = v.x + v.y + v.z + v.w;
#pragma unroll
    for (int o = 16; o > 0; o >>= 1)
        s += __shfl_xor_sync(0xffffffff, s, o);
    __syncthreads();
    if (lane == 0) red[wid] = s;
    __syncthreads();
    if (wid == 0) {
        float t = red[lane & 15];
#pragma unroll
        for (int o = 8; o > 0; o >>= 1)
            t += __shfl_xor_sync(0xffffffff, t, o);
        if (lane == 0) red[0] = t;
    }
    __syncthreads();
    const float inv = 1.f / red[0];

    __half2 o0, o1;
    o0.x = __float2half(v.x * inv); o0.y = __float2half(v.y * inv);
    o1.x = __float2half(v.z * inv); o1.y = __float2half(v.w * inv);
    __half2* dst = (__half2*)(P + base + tid * 4);
    dst[0] = o0; dst[1] = o1;
}

// ---------------------------------------------------------------------------
// Launch
// ---------------------------------------------------------------------------
extern "C" void kernel_launch(void* const* d_in, const int* in_sizes, int n_in,
                              void* d_out, int out_size)
{
    const float* x    = (const float*)d_in[0];
    const int*   adj  = (const int*)  d_in[1];
    const float* W    = (const float*)d_in[2];
    const float* bias = (const float*)d_in[3];
    const float* attn = (const float*)d_in[4];
    float* out = (float*)d_out;

    __half *x_hi, *x_lo, *w_hi, *w_lo, *at_hi, *at_lo;
    __half *h_hi, *h_lo, *ht_hi, *ha_hi, *ha_lo, *p;
    float* s;
    cudaGetSymbolAddress((void**)&x_hi,  g_x_hi);  cudaGetSymbolAddress((void**)&x_lo,  g_x_lo);
    cudaGetSymbolAddress((void**)&w_hi,  g_w_hi);  cudaGetSymbolAddress((void**)&w_lo,  g_w_lo);
    cudaGetSymbolAddress((void**)&at_hi, g_at_hi); cudaGetSymbolAddress((void**)&at_lo, g_at_lo);
    cudaGetSymbolAddress((void**)&h_hi,  g_h_hi);  cudaGetSymbolAddress((void**)&h_lo,  g_h_lo);
    cudaGetSymbolAddress((void**)&ht_hi, g_ht_hi);
    cudaGetSymbolAddress((void**)&ha_hi, g_ha_hi); cudaGetSymbolAddress((void**)&ha_lo, g_ha_lo);
    cudaGetSymbolAddress((void**)&p,     g_p);
    cudaGetSymbolAddress((void**)&s,     g_s);

    cudaFuncSetAttribute(k_mma<1>, cudaFuncAttributeMaxDynamicSharedMemorySize, SMEM_G3P);
    cudaFuncSetAttribute(k_mma<2>, cudaFuncAttributeMaxDynamicSharedMemorySize, SMEM_G3P);
    cudaFuncSetAttribute(k_mma<3>, cudaFuncAttributeMaxDynamicSharedMemorySize, SMEM_G3P);
    cudaFuncSetAttribute(k_mma<4>, cudaFuncAttributeMaxDynamicSharedMemorySize, SMEM_G4);

    // Input splits
    k_split<<<4096, 256>>>(x, x_hi, x_lo, MTOT * DQ);
    k_split<<<512, 256>>>(W, w_hi, w_lo, DQ * DQ);
    k_split_T<<<512, 256>>>(attn, at_hi, at_lo);

    // h = x @ W^T + b  (3-pass), hT_hi produced in epilogue
    k_mma<1><<<dim3(DQ / 128, MTOT / 128, 1), 128, SMEM_G3P>>>(
        x_hi, x_lo, w_hi, w_lo, bias, nullptr, nullptr, h_hi, h_lo, ht_hi);

    // ha = h @ attn  (3-pass)
    k_mma<2><<<dim3(DQ / 128, MTOT / 128, 1), 128, SMEM_G3P>>>(
        h_hi, h_lo, at_hi, at_lo, nullptr, nullptr, nullptr, ha_hi, ha_lo, nullptr);

    // scores = ha @ h^T (per batch), adjacency-masked  (3-pass)
    k_mma<3><<<dim3(NQ / 128, NQ / 128, BQ), 128, SMEM_G3P>>>(
        ha_hi, ha_lo, h_hi, h_lo, nullptr, adj, s, nullptr, nullptr, nullptr);

    // softmax rows -> P fp16
    k_softmax<<<BQ * NQ, 512>>>(s, p);

    // out = elu(P @ h) per batch  (1-pass: P fp16, hT_hi fp16)
    k_mma<4><<<dim3(DQ / 128, NQ / 128, BQ), 128, SMEM_G4>>>(
        p, p, ht_hi, ht_hi, nullptr, nullptr, out, nullptr, nullptr, nullptr);
}